// round 1
// baseline (speedup 1.0000x reference)
#include <cuda_runtime.h>
#include <math.h>

// Problem constants
#define Bb 4
#define Cc 512
#define NN_ 2048
#define Hh 8
#define Dd 64
#define BH (Bb*Hh)
#define BCN (Bb*Cc*NN_)

// Scratch (static device allocations; allowed path for scratch space)
__device__ float g_q[BCN];
__device__ float g_k[BCN];
__device__ float g_v[BCN];
__device__ float g_att[BCN];
__device__ float g_msg[BCN];
__device__ float g_cat[2*BCN];
__device__ float g_h[2*BCN];
__device__ float g_s[(size_t)BH*NN_*NN_];   // 512 MB score buffer

// ---------------------------------------------------------------------------
// Generic tiled GEMM: Y[b][m][n] = bias[m] + (res ? res[b][m][n] : 0)
//                                 + sum_k W[m][k] * X[b][k][n]
// Tile 64x64, K-step 16, 256 threads, 4x4 per thread.
// ---------------------------------------------------------------------------
__global__ void gemm_bias(const float* __restrict__ W, const float* __restrict__ bias,
                          const float* __restrict__ X, const float* __restrict__ res,
                          float* __restrict__ Y, int M, int K, int Nc)
{
    __shared__ float Ws[16][65];   // [k][m]
    __shared__ float Xs[16][64];   // [k][n]
    const int b  = blockIdx.z;
    const int m0 = blockIdx.y * 64;
    const int n0 = blockIdx.x * 64;
    const float* Xb = X + (size_t)b * K * Nc;

    const int tid = threadIdx.x;
    const int tx = tid & 15, ty = tid >> 4;

    float acc[4][4] = {};

    for (int k0 = 0; k0 < K; k0 += 16) {
        // load W tile -> Ws[k][m]
        {
            const int k = tid & 15, mb = tid >> 4;
            #pragma unroll
            for (int i = 0; i < 4; i++)
                Ws[k][mb + 16*i] = W[(size_t)(m0 + mb + 16*i) * K + k0 + k];
        }
        // load X tile -> Xs[k][n]
        {
            const int n = tid & 63, kb = tid >> 6;
            #pragma unroll
            for (int i = 0; i < 4; i++)
                Xs[kb + 4*i][n] = Xb[(size_t)(k0 + kb + 4*i) * Nc + n0 + n];
        }
        __syncthreads();
        #pragma unroll
        for (int k = 0; k < 16; k++) {
            float a[4], x[4];
            #pragma unroll
            for (int i = 0; i < 4; i++) a[i] = Ws[k][ty + 16*i];
            #pragma unroll
            for (int j = 0; j < 4; j++) x[j] = Xs[k][tx + 16*j];
            #pragma unroll
            for (int i = 0; i < 4; i++)
                #pragma unroll
                for (int j = 0; j < 4; j++)
                    acc[i][j] += a[i] * x[j];
        }
        __syncthreads();
    }

    #pragma unroll
    for (int i = 0; i < 4; i++) {
        const int m = m0 + ty + 16*i;
        const float bv = bias[m];
        #pragma unroll
        for (int j = 0; j < 4; j++) {
            const int n = n0 + tx + 16*j;
            const size_t idx = (size_t)b * M * Nc + (size_t)m * Nc + n;
            float v = acc[i][j] + bv;
            if (res) v += res[idx];
            Y[idx] = v;
        }
    }
}

// ---------------------------------------------------------------------------
// Attention scores: S[bh][n][m] = (1/8) * sum_d q[b, d*H+h, n] * k[b, d*H+h, m]
// ---------------------------------------------------------------------------
__global__ void attn_scores(const float* __restrict__ q, const float* __restrict__ k,
                            float* __restrict__ S)
{
    const int bh = blockIdx.z;
    const int b = bh >> 3, h = bh & 7;
    const int n0 = blockIdx.y * 64;
    const int m0 = blockIdx.x * 64;
    const float* qb = q + (size_t)b * Cc * NN_ + (size_t)h * NN_;
    const float* kb = k + (size_t)b * Cc * NN_ + (size_t)h * NN_;

    __shared__ float Qs[16][64];   // [d][n]
    __shared__ float Ks[16][64];   // [d][m]

    const int tid = threadIdx.x;
    const int tx = tid & 15, ty = tid >> 4;   // tx -> m, ty -> n

    float acc[4][4] = {};

    for (int d0 = 0; d0 < Dd; d0 += 16) {
        {
            const int c = tid & 63, db = tid >> 6;
            #pragma unroll
            for (int i = 0; i < 4; i++) {
                const int dd = db + 4*i;
                Qs[dd][c] = qb[(size_t)(d0 + dd) * Hh * NN_ + n0 + c];
                Ks[dd][c] = kb[(size_t)(d0 + dd) * Hh * NN_ + m0 + c];
            }
        }
        __syncthreads();
        #pragma unroll
        for (int d = 0; d < 16; d++) {
            float a[4], x[4];
            #pragma unroll
            for (int i = 0; i < 4; i++) a[i] = Qs[d][ty + 16*i];
            #pragma unroll
            for (int j = 0; j < 4; j++) x[j] = Ks[d][tx + 16*j];
            #pragma unroll
            for (int i = 0; i < 4; i++)
                #pragma unroll
                for (int j = 0; j < 4; j++)
                    acc[i][j] += a[i] * x[j];
        }
        __syncthreads();
    }

    float* Sb = S + (size_t)bh * NN_ * NN_;
    #pragma unroll
    for (int i = 0; i < 4; i++) {
        const int n = n0 + ty + 16*i;
        #pragma unroll
        for (int j = 0; j < 4; j++) {
            const int m = m0 + tx + 16*j;
            Sb[(size_t)n * NN_ + m] = acc[i][j] * 0.125f;
        }
    }
}

// ---------------------------------------------------------------------------
// Row softmax over last dim (length 2048). One block (256 threads) per row.
// ---------------------------------------------------------------------------
__global__ void softmax_rows(float* __restrict__ S)
{
    float* row = S + ((size_t)blockIdx.y * NN_ + blockIdx.x) * NN_;
    const int tid = threadIdx.x;
    __shared__ float red[8];

    float vals[8];
    float mx = -3.4e38f;
    #pragma unroll
    for (int i = 0; i < 8; i++) { vals[i] = row[tid + 256*i]; mx = fmaxf(mx, vals[i]); }

    #pragma unroll
    for (int o = 16; o > 0; o >>= 1) mx = fmaxf(mx, __shfl_xor_sync(0xffffffffu, mx, o));
    if ((tid & 31) == 0) red[tid >> 5] = mx;
    __syncthreads();
    if (tid < 8) {
        float v = red[tid];
        #pragma unroll
        for (int o = 4; o > 0; o >>= 1) v = fmaxf(v, __shfl_xor_sync(0xffu, v, o));
        if (tid == 0) red[0] = v;
    }
    __syncthreads();
    mx = red[0];
    __syncthreads();

    float s = 0.f;
    #pragma unroll
    for (int i = 0; i < 8; i++) { vals[i] = __expf(vals[i] - mx); s += vals[i]; }

    #pragma unroll
    for (int o = 16; o > 0; o >>= 1) s += __shfl_xor_sync(0xffffffffu, s, o);
    if ((tid & 31) == 0) red[tid >> 5] = s;
    __syncthreads();
    if (tid < 8) {
        float v = red[tid];
        #pragma unroll
        for (int o = 4; o > 0; o >>= 1) v += __shfl_xor_sync(0xffu, v, o);
        if (tid == 0) red[0] = v;
    }
    __syncthreads();
    const float inv = 1.f / red[0];

    #pragma unroll
    for (int i = 0; i < 8; i++) row[tid + 256*i] = vals[i] * inv;
}

// ---------------------------------------------------------------------------
// out[b, d*H+h, n] = sum_m P[bh][n][m] * v[b, d*H+h, m]
// Tile: full d (64 rows) x 64 n-cols, K-step 16 over m.
// ---------------------------------------------------------------------------
__global__ void attn_pv(const float* __restrict__ S, const float* __restrict__ v,
                        float* __restrict__ out)
{
    const int bh = blockIdx.z;
    const int b = bh >> 3, h = bh & 7;
    const int n0 = blockIdx.x * 64;
    const float* Sb = S + (size_t)bh * NN_ * NN_;
    const float* vb = v + (size_t)b * Cc * NN_ + (size_t)h * NN_;

    __shared__ float Ps[16][65];   // [m][n]
    __shared__ float Vs[16][65];   // [m][d]

    const int tid = threadIdx.x;
    const int tx = tid & 15, ty = tid >> 4;   // tx -> n, ty -> d

    float acc[4][4] = {};

    for (int m0 = 0; m0 < NN_; m0 += 16) {
        {
            const int mm = tid & 15, rb = tid >> 4;
            #pragma unroll
            for (int i = 0; i < 4; i++) {
                const int r = rb + 16*i;
                Ps[mm][r] = Sb[(size_t)(n0 + r) * NN_ + m0 + mm];
                Vs[mm][r] = vb[(size_t)r * Hh * NN_ + m0 + mm];
            }
        }
        __syncthreads();
        #pragma unroll
        for (int mm = 0; mm < 16; mm++) {
            float a[4], x[4];
            #pragma unroll
            for (int i = 0; i < 4; i++) a[i] = Vs[mm][ty + 16*i];
            #pragma unroll
            for (int j = 0; j < 4; j++) x[j] = Ps[mm][tx + 16*j];
            #pragma unroll
            for (int i = 0; i < 4; i++)
                #pragma unroll
                for (int j = 0; j < 4; j++)
                    acc[i][j] += a[i] * x[j];
        }
        __syncthreads();
    }

    #pragma unroll
    for (int i = 0; i < 4; i++) {
        const int d = ty + 16*i;
        #pragma unroll
        for (int j = 0; j < 4; j++) {
            const int n = n0 + tx + 16*j;
            out[(size_t)b * Cc * NN_ + (size_t)(d * Hh + h) * NN_ + n] = acc[i][j];
        }
    }
}

// ---------------------------------------------------------------------------
// Concat along channels: cat[b][0:512] = a, cat[b][512:1024] = m
// ---------------------------------------------------------------------------
__global__ void concat2(const float* __restrict__ a, const float* __restrict__ msg,
                        float* __restrict__ cat)
{
    const size_t total = (size_t)2 * BCN;
    for (size_t idx = (size_t)blockIdx.x * blockDim.x + threadIdx.x; idx < total;
         idx += (size_t)gridDim.x * blockDim.x) {
        const size_t b = idx / ((size_t)2 * Cc * NN_);
        const size_t r = idx % ((size_t)2 * Cc * NN_);
        const size_t c = r / NN_;
        const size_t n = r % NN_;
        float v;
        if (c < Cc) v = a[b * Cc * NN_ + c * NN_ + n];
        else        v = msg[b * Cc * NN_ + (c - Cc) * NN_ + n];
        cat[idx] = v;
    }
}

// ---------------------------------------------------------------------------
// InstanceNorm (over length dim) + ReLU, in place. One block per (b, ch) row.
// ---------------------------------------------------------------------------
__global__ void inorm_relu(float* __restrict__ X)
{
    float* row = X + (size_t)blockIdx.x * NN_;
    const int tid = threadIdx.x;
    __shared__ float redA[8], redB[8];

    float v[8];
    float s = 0.f, s2 = 0.f;
    #pragma unroll
    for (int i = 0; i < 8; i++) { v[i] = row[tid + 256*i]; s += v[i]; s2 += v[i]*v[i]; }

    #pragma unroll
    for (int o = 16; o > 0; o >>= 1) {
        s  += __shfl_xor_sync(0xffffffffu, s, o);
        s2 += __shfl_xor_sync(0xffffffffu, s2, o);
    }
    if ((tid & 31) == 0) { redA[tid >> 5] = s; redB[tid >> 5] = s2; }
    __syncthreads();
    if (tid < 8) {
        float a = redA[tid], b = redB[tid];
        #pragma unroll
        for (int o = 4; o > 0; o >>= 1) {
            a += __shfl_xor_sync(0xffu, a, o);
            b += __shfl_xor_sync(0xffu, b, o);
        }
        if (tid == 0) { redA[0] = a; redB[0] = b; }
    }
    __syncthreads();
    const float mean = redA[0] * (1.f / NN_);
    const float var  = redB[0] * (1.f / NN_) - mean * mean;
    const float inv  = rsqrtf(var + 1e-5f);

    #pragma unroll
    for (int i = 0; i < 8; i++) {
        float y = (v[i] - mean) * inv;
        row[tid + 256*i] = y > 0.f ? y : 0.f;
    }
}

// ---------------------------------------------------------------------------
// One full pipeline pass: A = query-side input, KV = key/value-side input.
// dst = A + MLP(concat(A, Wm @ Attn(A, KV)))
// ---------------------------------------------------------------------------
static void run_pass(const float* A, const float* KV, float* dst,
                     const float* Wq, const float* bq, const float* Wk, const float* bk,
                     const float* Wv, const float* bv, const float* Wm, const float* bm,
                     const float* W1, const float* b1, const float* W2, const float* b2,
                     float* q, float* k, float* v, float* att, float* msg,
                     float* cat, float* hb, float* sc)
{
    dim3 g512(NN_/64, Cc/64, Bb);
    gemm_bias<<<g512, 256>>>(Wq, bq, A,  nullptr, q, Cc, Cc, NN_);
    gemm_bias<<<g512, 256>>>(Wk, bk, KV, nullptr, k, Cc, Cc, NN_);
    gemm_bias<<<g512, 256>>>(Wv, bv, KV, nullptr, v, Cc, Cc, NN_);

    attn_scores<<<dim3(NN_/64, NN_/64, BH), 256>>>(q, k, sc);
    softmax_rows<<<dim3(NN_, BH), 256>>>(sc);
    attn_pv<<<dim3(NN_/64, 1, BH), 256>>>(sc, v, att);

    gemm_bias<<<g512, 256>>>(Wm, bm, att, nullptr, msg, Cc, Cc, NN_);

    concat2<<<4096, 256>>>(A, msg, cat);
    gemm_bias<<<dim3(NN_/64, 2*Cc/64, Bb), 256>>>(W1, b1, cat, nullptr, hb, 2*Cc, 2*Cc, NN_);
    inorm_relu<<<Bb * 2 * Cc, 256>>>(hb);
    gemm_bias<<<g512, 256>>>(W2, b2, hb, A, dst, Cc, 2*Cc, NN_);
}

extern "C" void kernel_launch(void* const* d_in, const int* in_sizes, int n_in,
                              void* d_out, int out_size)
{
    const float* src = (const float*)d_in[0];
    const float* tgt = (const float*)d_in[1];
    const float* Wq = (const float*)d_in[2];   const float* bq = (const float*)d_in[3];
    const float* Wk = (const float*)d_in[4];   const float* bk = (const float*)d_in[5];
    const float* Wv = (const float*)d_in[6];   const float* bv = (const float*)d_in[7];
    const float* Wm = (const float*)d_in[8];   const float* bm = (const float*)d_in[9];
    const float* W1 = (const float*)d_in[10];  const float* b1 = (const float*)d_in[11];
    const float* W2 = (const float*)d_in[12];  const float* b2 = (const float*)d_in[13];

    float* out = (float*)d_out;
    float* out_src = out;
    float* out_tgt = out + (size_t)BCN;

    float *q, *k, *v, *att, *msg, *cat, *hb, *sc;
    cudaGetSymbolAddress((void**)&q,   g_q);
    cudaGetSymbolAddress((void**)&k,   g_k);
    cudaGetSymbolAddress((void**)&v,   g_v);
    cudaGetSymbolAddress((void**)&att, g_att);
    cudaGetSymbolAddress((void**)&msg, g_msg);
    cudaGetSymbolAddress((void**)&cat, g_cat);
    cudaGetSymbolAddress((void**)&hb,  g_h);
    cudaGetSymbolAddress((void**)&sc,  g_s);

    // Pass 1: update src using ORIGINAL target
    run_pass(src, tgt, out_src,
             Wq, bq, Wk, bk, Wv, bv, Wm, bm, W1, b1, W2, b2,
             q, k, v, att, msg, cat, hb, sc);

    // Pass 2: update tgt using UPDATED source
    run_pass(tgt, out_src, out_tgt,
             Wq, bq, Wk, bk, Wv, bv, Wm, bm, W1, b1, W2, b2,
             q, k, v, att, msg, cat, hb, sc);
}